// round 1
// baseline (speedup 1.0000x reference)
#include <cuda_runtime.h>
#include <math.h>

#define BB 2
#define HH 16
#define SS 2048
#define HD 128
#define DD 2048
#define KKEEP 819
#define NEGV -1e9f
#define QT 8

// Scratch (device globals: no allocation allowed)
__device__ float g_q [BB*HH*SS*HD];   // [bh][s][d]
__device__ float g_kT[BB*HH*HD*SS];   // [bh][d][t]  (transposed K)
__device__ float g_v [BB*HH*SS*HD];   // [bh][t][d]
__device__ float g_att[BB*SS*DD];     // [b][s][h*HD+d]

// ---------------------------------------------------------------------------
// Kernel 1: per-head QKV projections. y = x @ W^T + b  (torch Linear layout)
// ---------------------------------------------------------------------------
__global__ __launch_bounds__(256) void qkv_kernel(
    const float* __restrict__ x,
    const float* __restrict__ Wq, const float* __restrict__ Wk, const float* __restrict__ Wv,
    const float* __restrict__ bq, const float* __restrict__ bk, const float* __restrict__ bv)
{
    __shared__ float xs[64][HD];
    __shared__ float Ws[16][HD + 1];

    int bh = blockIdx.y;
    int b  = bh >> 4, h = bh & 15;
    int s0 = blockIdx.x * 64;
    int tid = threadIdx.x;

    const float* xbase = x + ((size_t)b*SS + s0)*DD + h*HD;
    for (int i = tid; i < 64*32; i += 256) {
        int sr = i >> 5, dv = (i & 31) << 2;
        float4 val = *(const float4*)(xbase + (size_t)sr*DD + dv);
        xs[sr][dv+0] = val.x; xs[sr][dv+1] = val.y;
        xs[sr][dv+2] = val.z; xs[sr][dv+3] = val.w;
    }

    int ei = tid & 15, si = tid >> 4;

    for (int w = 0; w < 3; w++) {
        const float* Wh   = ((w==0) ? Wq : (w==1) ? Wk : Wv) + (size_t)h*HD*HD;
        const float* bias = ((w==0) ? bq : (w==1) ? bk : bv) + h*HD;
        for (int et = 0; et < 8; et++) {
            __syncthreads();
            for (int i = tid; i < 512; i += 256) {
                int er = i >> 5, dv = (i & 31) << 2;
                float4 val = *(const float4*)(Wh + (size_t)(et*16 + er)*HD + dv);
                Ws[er][dv+0] = val.x; Ws[er][dv+1] = val.y;
                Ws[er][dv+2] = val.z; Ws[er][dv+3] = val.w;
            }
            __syncthreads();
            float a0 = 0.f, a1 = 0.f, a2 = 0.f, a3 = 0.f;
            #pragma unroll 8
            for (int d = 0; d < HD; d++) {
                float wv = Ws[ei][d];
                a0 += xs[si     ][d] * wv;
                a1 += xs[si + 16][d] * wv;
                a2 += xs[si + 32][d] * wv;
                a3 += xs[si + 48][d] * wv;
            }
            int e = et*16 + ei;
            float bbv = bias[e];
            a0 += bbv; a1 += bbv; a2 += bbv; a3 += bbv;
            if (w == 1) {
                float* kp = g_kT + ((size_t)bh*HD + e)*SS + s0;
                kp[si] = a0; kp[si+16] = a1; kp[si+32] = a2; kp[si+48] = a3;
            } else {
                float* op = (w == 0 ? g_q : g_v) + ((size_t)bh*SS + s0)*HD + e;
                op[(size_t)(si     )*HD] = a0;
                op[(size_t)(si + 16)*HD] = a1;
                op[(size_t)(si + 32)*HD] = a2;
                op[(size_t)(si + 48)*HD] = a3;
            }
        }
    }
}

// ---------------------------------------------------------------------------
// Kernel 2: scores + exact top-k threshold + softmax + attn@V  (8 rows/block)
// ---------------------------------------------------------------------------
__device__ __forceinline__ unsigned f2key(float f) {
    unsigned u = __float_as_uint(f);
    return u ^ ((u & 0x80000000u) ? 0xFFFFFFFFu : 0x80000000u);
}
__device__ __forceinline__ float key2f(unsigned k) {
    unsigned u = (k & 0x80000000u) ? (k ^ 0x80000000u) : ~k;
    return __uint_as_float(u);
}

__global__ __launch_bounds__(256) void attn_kernel()
{
    extern __shared__ float smem[];
    float* sc   = smem;                   // [QT][SS]   scores -> weights
    float* q_s  = sc  + QT*SS;            // [QT][HD]
    float* outp = q_s + QT*HD;            // [QT][HD]   partial V-accum
    int*   hist = (int*)(outp + QT*HD);   // [256]
    int*   scn  = hist + 256;             // [256]
    float* red  = (float*)(scn + 256);    // [256]
    __shared__ float rsinv_s[QT];
    __shared__ int sel_bin, sel_K;

    int bh  = blockIdx.y;
    int s0  = blockIdx.x * QT;
    int tid = threadIdx.x;
    int smax = s0 + QT - 1;

    const float* qg = g_q + ((size_t)bh*SS + s0)*HD;
    for (int i = tid; i < QT*HD; i += 256) q_s[i] = qg[i];
    __syncthreads();

    // ---- Phase A: scores (causal-bounded) ----
    const float* kTg = g_kT + (size_t)bh*HD*SS;
    const float scale = 0.08838834764831845f;  // 1/sqrt(128)
    for (int j = 0; j < SS/256; j++) {
        int t = tid + j*256;
        if (t <= smax) {
            float acc[QT];
            #pragma unroll
            for (int r = 0; r < QT; r++) acc[r] = 0.f;
            #pragma unroll 4
            for (int d = 0; d < HD; d++) {
                float kv = kTg[(size_t)d*SS + t];
                #pragma unroll
                for (int r = 0; r < QT; r++) acc[r] += q_s[r*HD + d] * kv;
            }
            #pragma unroll
            for (int r = 0; r < QT; r++)
                sc[r*SS + t] = (t <= s0 + r) ? acc[r]*scale : NEGV;
        } else {
            #pragma unroll
            for (int r = 0; r < QT; r++) sc[r*SS + t] = NEGV;
        }
    }
    __syncthreads();

    // ---- Phase B+C per row: radix-select kth largest, then softmax ----
    for (int r = 0; r < QT; r++) {
        float* row = sc + r*SS;
        unsigned prefix = 0; int K = KKEEP;
        for (int pass = 0; pass < 4; pass++) {
            int shift = 24 - pass*8;
            hist[tid] = 0;
            __syncthreads();
            for (int t = tid; t < SS; t += 256) {
                unsigned key = f2key(row[t]);
                bool cand = (pass == 0) || (((key ^ prefix) >> (shift + 8)) == 0u);
                if (cand) atomicAdd(&hist[(key >> shift) & 255u], 1);
            }
            __syncthreads();
            scn[tid] = hist[tid];
            __syncthreads();
            for (int off = 1; off < 256; off <<= 1) {
                int v = (tid + off < 256) ? scn[tid + off] : 0;
                __syncthreads();
                scn[tid] += v;
                __syncthreads();
            }
            int above = (tid < 255) ? scn[tid + 1] : 0;
            if (scn[tid] >= K && above < K) { sel_bin = tid; sel_K = K - above; }
            __syncthreads();
            prefix |= ((unsigned)sel_bin) << shift;
            K = sel_K;
        }
        float thr = key2f(prefix);

        // row max
        float lm = -3.4e38f;
        for (int t = tid; t < SS; t += 256) lm = fmaxf(lm, row[t]);
        red[tid] = lm; __syncthreads();
        for (int st = 128; st > 0; st >>= 1) {
            if (tid < st) red[tid] = fmaxf(red[tid], red[tid + st]);
            __syncthreads();
        }
        float rmax = red[0];
        __syncthreads();

        // weights + sum
        float ls = 0.f;
        for (int t = tid; t < SS; t += 256) {
            float v = row[t];
            float wv = (v >= thr) ? expf(v - rmax) : 0.f;
            row[t] = wv; ls += wv;
        }
        red[tid] = ls; __syncthreads();
        for (int st = 128; st > 0; st >>= 1) {
            if (tid < st) red[tid] += red[tid + st];
            __syncthreads();
        }
        if (tid == 0) rsinv_s[r] = 1.f / red[0];
        __syncthreads();
    }

    // ---- Phase D: out = attn @ V ----
    int d = tid & 127, half = tid >> 7;
    int tend = smax + 1;
    const float* vg = g_v + (size_t)bh*SS*HD + d;
    float acc[QT];
    #pragma unroll
    for (int r = 0; r < QT; r++) acc[r] = 0.f;
    for (int t = half; t < tend; t += 2) {
        float vv = vg[(size_t)t*HD];
        #pragma unroll
        for (int r = 0; r < QT; r++) acc[r] += sc[r*SS + t] * vv;
    }
    if (half) {
        #pragma unroll
        for (int r = 0; r < QT; r++) outp[r*HD + d] = acc[r];
    }
    __syncthreads();
    if (!half) {
        int b = bh >> 4, h = bh & 15;
        #pragma unroll
        for (int r = 0; r < QT; r++) {
            float o = (acc[r] + outp[r*HD + d]) * rsinv_s[r];
            g_att[((size_t)b*SS + s0 + r)*DD + h*HD + d] = o;
        }
    }
}

// ---------------------------------------------------------------------------
// Kernel 3: out[b,i,t] = sum_s g_att[b,s,i] * Wo[t,s] + bo[t]
// ---------------------------------------------------------------------------
__global__ __launch_bounds__(256) void proj_kernel(
    const float* __restrict__ Wo, const float* __restrict__ bo,
    float* __restrict__ out)
{
    __shared__ float As[8][128];
    __shared__ float Bs[8][128];

    int b  = blockIdx.z;
    int i0 = blockIdx.y * 128;
    int t0 = blockIdx.x * 128;
    int tid = threadIdx.x;
    int tx = tid & 15, ty = tid >> 4;

    float acc[8][8];
    #pragma unroll
    for (int i = 0; i < 8; i++)
        #pragma unroll
        for (int j = 0; j < 8; j++) acc[i][j] = 0.f;

    const float* Ab = g_att + (size_t)b*SS*DD;

    int kkA = tid >> 5, c4A = (tid & 31) << 2;
    int ttB = tid >> 1, ccB = (tid & 1) << 2;

    for (int k0 = 0; k0 < SS; k0 += 8) {
        __syncthreads();
        {
            float4 av = *(const float4*)(Ab + (size_t)(k0 + kkA)*DD + i0 + c4A);
            As[kkA][c4A+0] = av.x; As[kkA][c4A+1] = av.y;
            As[kkA][c4A+2] = av.z; As[kkA][c4A+3] = av.w;
            float4 bv = *(const float4*)(Wo + (size_t)(t0 + ttB)*SS + k0 + ccB);
            Bs[ccB+0][ttB] = bv.x; Bs[ccB+1][ttB] = bv.y;
            Bs[ccB+2][ttB] = bv.z; Bs[ccB+3][ttB] = bv.w;
        }
        __syncthreads();
        #pragma unroll
        for (int kk = 0; kk < 8; kk++) {
            float a[8], bbv[8];
            #pragma unroll
            for (int i = 0; i < 8; i++) a[i]   = As[kk][ty*8 + i];
            #pragma unroll
            for (int j = 0; j < 8; j++) bbv[j] = Bs[kk][tx*8 + j];
            #pragma unroll
            for (int i = 0; i < 8; i++)
                #pragma unroll
                for (int j = 0; j < 8; j++) acc[i][j] += a[i] * bbv[j];
        }
    }

    float bias[8];
    #pragma unroll
    for (int j = 0; j < 8; j++) bias[j] = bo[t0 + tx*8 + j];
    #pragma unroll
    for (int i = 0; i < 8; i++) {
        float* op = out + ((size_t)b*DD + i0 + ty*8 + i)*DD + t0 + tx*8;
        #pragma unroll
        for (int j = 0; j < 8; j++) op[j] = acc[i][j] + bias[j];
    }
}

// ---------------------------------------------------------------------------
extern "C" void kernel_launch(void* const* d_in, const int* in_sizes, int n_in,
                              void* d_out, int out_size)
{
    const float* x  = (const float*)d_in[0];
    // d_in[1] = causal_mask (unused; mask computed analytically)
    const float* Wq = (const float*)d_in[2];
    const float* Wk = (const float*)d_in[3];
    const float* Wv = (const float*)d_in[4];
    const float* bq = (const float*)d_in[5];
    const float* bk = (const float*)d_in[6];
    const float* bv = (const float*)d_in[7];
    const float* Wo = (const float*)d_in[8];
    const float* bo = (const float*)d_in[9];
    float* out = (float*)d_out;

    const int SMEM2 = (QT*SS + 2*QT*HD)*4 + 256*4*2 + 256*4;  // 76800 bytes

    qkv_kernel<<<dim3(SS/64, BB*HH), 256>>>(x, Wq, Wk, Wv, bq, bk, bv);

    cudaFuncSetAttribute(attn_kernel, cudaFuncAttributeMaxDynamicSharedMemorySize, SMEM2);
    attn_kernel<<<dim3(SS/QT, BB*HH), 256, SMEM2>>>();

    proj_kernel<<<dim3(DD/128, DD/128, BB), 256>>>(Wo, bo, out);
}